// round 9
// baseline (speedup 1.0000x reference)
#include <cuda_runtime.h>
#include <cstdint>

#define BB      48
#define NKC     800
#define NMBON   20
#define NFBN    60
#define NDAN    20
#define NREC    100
#define TT      121
#define NSTEP   120
#define W_MAXC  0.05f

#define NTHREADS 512
#define NCTA     (BB * 2)

__device__ float g_rkcT[(long)BB * TT * NKC];

// ---------------------------------------------------------------------------
// Transpose r_kc [B, NKC, T] -> g_rkcT [B, T, NKC]
// ---------------------------------------------------------------------------
__global__ void transpose_kernel(const float* __restrict__ rkc) {
    __shared__ float tile[32][33];
    const int bz = blockIdx.z;
    const int kt = blockIdx.y;
    const int tt = blockIdx.x;
    const int tx = threadIdx.x, ty = threadIdx.y;

    int k = kt * 32 + ty;
    int t = tt * 32 + tx;
    if (t < TT)
        tile[ty][tx] = rkc[((long)bz * NKC + k) * TT + t];
    __syncthreads();
    int t2 = tt * 32 + ty;
    int k2 = kt * 32 + tx;
    if (t2 < TT)
        g_rkcT[((long)bz * TT + t2) * NKC + k2] = tile[tx][ty];
}

// ---------------------------------------------------------------------------
// PASS 1: r-dynamics only (R7 structure, W/wt state kept in registers for
// I_mbon but NEVER stored). Outputs: r_all, ro_all.
// ---------------------------------------------------------------------------
#define SM_FLOATS (4 + 40 + 10000 + 2400 + 1600 + 200 + 100 + 128 + 80 + 20 + 20 + 20 + 120)

__global__ __launch_bounds__(NTHREADS, 1) __cluster_dims__(2, 1, 1)
void rnn_kernel(
    const float* __restrict__ r_ext,
    const float* __restrict__ time_arr,
    const float* __restrict__ W_kc0,
    const float* __restrict__ wt0,
    const float* __restrict__ W_recur,
    const float* __restrict__ W_readout,
    const float* __restrict__ bias,
    const float* __restrict__ W_ext,
    float* __restrict__ out)
{
    extern __shared__ float sm[];
    float* mbar_f  = sm;                  // 4
    float* imb     = sm + 4;              // 2 x 20
    float* WrM     = imb + 40;            // 100 x 100 row-major
    float* rkc3    = WrM + 10000;         // 3 x 800 ring
    float* rbkc    = rkc3 + 2400;         // 2 x 800
    float* r_s     = rbkc + 1600;         // 2 x 100
    float* bias_s  = r_s + 200;           // 100
    float* ifbn    = bias_s + 100;        // 2 x 64
    float* red_s   = ifbn + 128;          // 8 slots x 10 (slot 7 stays 0)
    float* rdan_s  = red_s + 80;          // 20
    float* rbdan_s = rdan_s + 20;         // 20
    float* wro_s   = rbdan_s + 20;        // 20
    float* wext_s  = wro_s + 20;          // 120

    const int tid  = threadIdx.x;
    const int bx   = blockIdx.x;
    const int b    = bx >> 1;
    const int rank = bx & 1;
    const int prank = rank ^ 1;
    const int m_off = rank * 10;
    const int lane = tid & 31;
    const int warp = tid >> 5;
    const int g    = tid >> 8;
    const int q    = tid & 255;
    const bool owner = (q < 200);

    int ci2 = -1;
    bool is_loc = false, is_peer = false;
    if (warp == 7) {
        if (lane < 10)      { ci2 = m_off + lane;            is_loc  = true; }
        else if (lane < 20) { ci2 = (m_off ^ 10) + lane - 10; is_peer = true; }
        else                { ci2 = 20 + (lane - 20); }
    } else if (warp == 15) {
        if (lane < 24) ci2 = 32 + lane;
    } else if (warp == 6) {
        if (lane >= 8 && lane < 20) ci2 = 56 + (lane - 8);
    } else if (warp == 14) {
        if (lane >= 8 && lane < 20) ci2 = 68 + (lane - 8);
    }

    float* out_r  = out;
    float* out_ro = out + (long)TT * BB * NREC + 2L * TT * BB * NMBON * NKC;

    const float dt  = time_arr[1] - time_arr[0];
    const float a_r = dt;
    const float a_w = dt * 0.2f;

    const float* rkc_g = g_rkcT + (long)b * TT * NKC;

    const uint32_t imb_loc  = (uint32_t)__cvta_generic_to_shared(imb);
    const uint32_t mbar_loc = (uint32_t)__cvta_generic_to_shared(mbar_f);
    uint32_t imb_rem, mbar_rem;
    asm("mapa.shared::cluster.u32 %0, %1, %2;" : "=r"(imb_rem)  : "r"(imb_loc),  "r"(prank));
    asm("mapa.shared::cluster.u32 %0, %1, %2;" : "=r"(mbar_rem) : "r"(mbar_loc), "r"(prank));

    if (tid == 0) {
        asm volatile("mbarrier.init.shared.b64 [%0], 10;" :: "r"(mbar_loc)     : "memory");
        asm volatile("mbarrier.init.shared.b64 [%0], 10;" :: "r"(mbar_loc + 8) : "memory");
    }
    for (int idx = tid; idx < NREC * NREC; idx += NTHREADS) {
        int i = idx / NREC, j = idx % NREC;
        float v = W_recur[idx];
        if (i < NMBON && j >= NREC - NDAN) v = 0.f;
        WrM[idx] = v;
    }
    if (tid < 80)       red_s[tid] = 0.f;
    if (tid < NREC)     bias_s[tid] = bias[tid];
    if (tid < NMBON)    wro_s[tid]  = W_readout[tid];
    if (tid >= 128 && tid < 128 + NFBN * 2) wext_s[tid - 128] = W_ext[tid - 128];
    if (tid < NREC) {
        float r0 = (tid < NMBON) ? 0.f : 0.1f;
        r_s[tid] = r0;
        if (rank == 0) out_r[(long)b * NREC + tid] = r0;
    }
    if (tid < NDAN) rbdan_s[tid] = 0.1f;
    for (int k = tid; k < NKC; k += NTHREADS) {
        float v = rkc_g[k];
        rkc3[k] = v;
        rbkc[800 + k] = v;
    }
    __syncthreads();
    if (tid < NFBN) {
        float e0 = r_ext[((long)b * 2 + 0) * TT];
        float e1 = r_ext[((long)b * 2 + 1) * TT];
        ifbn[tid] = wext_s[tid * 2] * e0 + wext_s[tid * 2 + 1] * e1;
    }
    if (tid == 0 && rank == 0) out_ro[b] = 0.f;

    float4 Wv[5], wtv[5];
    if (owner) {
        const long ibase = ((long)b * NMBON + m_off + g * 5) * NKC + q * 4;
#pragma unroll
        for (int mm = 0; mm < 5; ++mm) {
            Wv[mm]  = *(const float4*)(W_kc0 + ibase + (long)mm * NKC);
            wtv[mm] = *(const float4*)(wt0   + ibase + (long)mm * NKC);
        }
    } else {
#pragma unroll
        for (int mm = 0; mm < 5; ++mm) {
            Wv[mm]  = make_float4(0.f, 0.f, 0.f, 0.f);
            wtv[mm] = make_float4(0.f, 0.f, 0.f, 0.f);
        }
    }
    __syncthreads();
    asm volatile("barrier.cluster.arrive.aligned;" ::: "memory");
    asm volatile("barrier.cluster.wait.aligned;"   ::: "memory");

    int pcur = 0;
    for (int t = 0; t < NSTEP; ++t) {
        const int pnext = (pcur == 2) ? 0 : pcur + 1;
        const int hb  = t & 1;
        const int par = (t >> 1) & 1;

        const float* rc = r_s + hb * NREC;
        float* rn_buf   = r_s + (hb ^ 1) * NREC;

        // pre-bar1: B ∥ DAN-C (warp7) ∥ staging (warp15)
        if ((warp & 7) != 7) {
            float4 kc = make_float4(0.f, 0.f, 0.f, 0.f);
            if (owner) kc = *(const float4*)(rkc3 + pcur * 800 + q * 4);
#pragma unroll
            for (int mm = 0; mm < 5; ++mm) {
                float4 w = Wv[mm];
                float p = w.x * kc.x + w.y * kc.y + w.z * kc.z + w.w * kc.w;
                p += __shfl_xor_sync(0xffffffffu, p, 16);
                p += __shfl_xor_sync(0xffffffffu, p, 8);
                p += __shfl_xor_sync(0xffffffffu, p, 4);
                p += __shfl_xor_sync(0xffffffffu, p, 2);
                p += __shfl_xor_sync(0xffffffffu, p, 1);
                if (lane == 0)
                    red_s[(warp & 7) * 10 + g * 5 + mm] = p;
            }
        } else if (warp == 7) {
            if (lane < NDAN) {
                const int i = 80 + lane;
                const float4* wrow = (const float4*)(WrM + i * NREC);
                const float4* r4   = (const float4*)rc;
                float a0 = 0.f, a1 = 0.f, a2 = 0.f, a3 = 0.f;
#pragma unroll
                for (int jb = 0; jb < 25; ++jb) {
                    float4 wv = wrow[jb];
                    float4 rv = r4[jb];
                    a0 = fmaf(wv.x, rv.x, a0);
                    a1 = fmaf(wv.y, rv.y, a1);
                    a2 = fmaf(wv.z, rv.z, a2);
                    a3 = fmaf(wv.w, rv.w, a3);
                }
                float pre  = (a0 + a1) + (a2 + a3) + bias_s[i];
                float relu = fmaxf(pre, 0.f);
                float rold = rc[i];
                float rn   = fmaf(a_r, relu - rold, rold);
                rn_buf[i] = rn;
                if (rank == 0) out_r[((long)(t + 1) * BB + b) * NREC + i] = rn;
                rdan_s[lane] = rn;
                float rb = rbdan_s[lane];
                rbdan_s[lane] = fmaf(a_w, rn - rb, rb);
            }
        } else {
            const float* gsrc = rkc_g + (long)(t + 1) * NKC;
#pragma unroll
            for (int j = 0; j < 7; ++j) {
                int c = lane + 32 * j;
                if (c < 200) {
                    uint32_t dst = (uint32_t)__cvta_generic_to_shared(rkc3 + pnext * 800 + c * 4);
                    asm volatile("cp.async.cg.shared.global [%0], [%1], 16;\n"
                                 :: "r"(dst), "l"(gsrc + c * 4));
                }
            }
            asm volatile("cp.async.commit_group;\n" ::: "memory");
            float e0 = r_ext[((long)b * 2 + 0) * TT + (t + 1)];
            float e1 = r_ext[((long)b * 2 + 1) * TT + (t + 1)];
#pragma unroll
            for (int j = 0; j < 7; ++j) {
                int c = lane + 32 * j;
                if (c < 200) {
                    float4 kc = *(const float4*)(rkc3 + pcur * 800 + c * 4);
                    float4 bk = *(const float4*)(rbkc + (hb ^ 1) * 800 + c * 4);
                    bk.x = fmaf(a_w, kc.x - bk.x, bk.x);
                    bk.y = fmaf(a_w, kc.y - bk.y, bk.y);
                    bk.z = fmaf(a_w, kc.z - bk.z, bk.z);
                    bk.w = fmaf(a_w, kc.w - bk.w, bk.w);
                    *(float4*)(rbkc + hb * 800 + c * 4) = bk;
                }
            }
            {
                int f = lane;
                ifbn[(hb ^ 1) * 64 + f] = wext_s[f * 2] * e0 + wext_s[f * 2 + 1] * e1;
                f = lane + 32;
                if (f < NFBN)
                    ifbn[(hb ^ 1) * 64 + f] = wext_s[f * 2] * e0 + wext_s[f * 2 + 1] * e1;
            }
        }
        __syncthreads();   // bar1

        // post-bar1: send, then D-compute (NO stores) ∥ C dots ∥ cp wait
        float vloc = 0.f;
        if (warp == 7 && lane < 10) {
            vloc = red_s[0 * 10 + lane] + red_s[1 * 10 + lane] + red_s[2 * 10 + lane]
                 + red_s[3 * 10 + lane] + red_s[4 * 10 + lane] + red_s[5 * 10 + lane]
                 + red_s[6 * 10 + lane];
            asm volatile("st.shared::cluster.f32 [%0], %1;"
                         :: "r"(imb_rem + (hb * 20 + m_off + lane) * 4), "f"(vloc) : "memory");
            asm volatile("mbarrier.arrive.release.cluster.shared::cluster.b64 _, [%0];"
                         :: "r"(mbar_rem + hb * 8) : "memory");
        }

        if (owner) {
            // D-compute only: evolve W/wt in registers (feeds B(t+1))
            float4 kc = *(const float4*)(rkc3 + pcur * 800 + q * 4);
            float4 bk = *(const float4*)(rbkc + hb * 800 + q * 4);
#pragma unroll
            for (int mm = 0; mm < 5; ++mm) {
                const int m = m_off + g * 5 + mm;
                const float rbd = rbdan_s[m];
                const float rd  = rdan_s[m];
                float4 w = Wv[mm], wt = wtv[mm];
                float dw;
                dw = fmaf(rbd, kc.x, -(rd * bk.x)); wt.x = fmaf(dw, dt, wt.x);
                dw = fmaf(rbd, kc.y, -(rd * bk.y)); wt.y = fmaf(dw, dt, wt.y);
                dw = fmaf(rbd, kc.z, -(rd * bk.z)); wt.z = fmaf(dw, dt, wt.z);
                dw = fmaf(rbd, kc.w, -(rd * bk.w)); wt.w = fmaf(dw, dt, wt.w);
                w.x = fminf(fmaxf(fmaf(a_w, wt.x - w.x, w.x), 0.f), W_MAXC);
                w.y = fminf(fmaxf(fmaf(a_w, wt.y - w.y, w.y), 0.f), W_MAXC);
                w.z = fminf(fmaxf(fmaf(a_w, wt.z - w.z, w.z), 0.f), W_MAXC);
                w.w = fminf(fmaxf(fmaf(a_w, wt.w - w.w, w.w), 0.f), W_MAXC);
                Wv[mm] = w; wtv[mm] = wt;
            }
        }

        if (ci2 >= 0) {
            const int i = ci2;
            const float4* wrow = (const float4*)(WrM + i * NREC);
            const float4* r4   = (const float4*)rc;
            float a0 = 0.f, a1 = 0.f, a2 = 0.f, a3 = 0.f;
#pragma unroll
            for (int jb = 0; jb < 25; ++jb) {
                float4 wv = wrow[jb];
                float4 rv = r4[jb];
                a0 = fmaf(wv.x, rv.x, a0);
                a1 = fmaf(wv.y, rv.y, a1);
                a2 = fmaf(wv.z, rv.z, a2);
                a3 = fmaf(wv.w, rv.w, a3);
            }
            float p = (a0 + a1) + (a2 + a3);
            float itot;
            if (is_loc) {
                itot = vloc;
            } else if (is_peer) {
                uint32_t done;
                asm volatile(
                    "{\n\t.reg .pred p;\n\t"
                    "mbarrier.try_wait.parity.acquire.cluster.shared::cta.b64 p, [%1], %2;\n\t"
                    "selp.b32 %0, 1, 0, p;\n\t}"
                    : "=r"(done) : "r"(mbar_loc + hb * 8), "r"(par) : "memory");
                while (!done) {
                    asm volatile(
                        "{\n\t.reg .pred p;\n\t"
                        "mbarrier.try_wait.parity.acquire.cluster.shared::cta.b64 p, [%1], %2, 0x989680;\n\t"
                        "selp.b32 %0, 1, 0, p;\n\t}"
                        : "=r"(done) : "r"(mbar_loc + hb * 8), "r"(par) : "memory");
                }
                itot = imb[hb * 20 + i];
            } else {
                itot = ifbn[hb * 64 + (i - NMBON)];
            }
            float pre  = p + bias_s[i] + itot;
            float relu = fmaxf(pre, 0.f);
            float rold = rc[i];
            float rn   = fmaf(a_r, relu - rold, rold);
            rn_buf[i] = rn;
            if (rank == 0) out_r[((long)(t + 1) * BB + b) * NREC + i] = rn;
        }

        if (warp == 15)
            asm volatile("cp.async.wait_group 0;\n" ::: "memory");

        __syncthreads();   // bar2

        if (warp == 0 && rank == 0) {
            float v = (lane < NMBON) ? rn_buf[lane] * wro_s[lane] : 0.f;
            v += __shfl_xor_sync(0xffffffffu, v, 16);
            v += __shfl_xor_sync(0xffffffffu, v, 8);
            v += __shfl_xor_sync(0xffffffffu, v, 4);
            v += __shfl_xor_sync(0xffffffffu, v, 2);
            v += __shfl_xor_sync(0xffffffffu, v, 1);
            if (lane == 0) out_ro[(long)(t + 1) * BB + b] = v;
        }
        pcur = pnext;
    }

    asm volatile("barrier.cluster.arrive.aligned;" ::: "memory");
    asm volatile("barrier.cluster.wait.aligned;"   ::: "memory");
}

// ---------------------------------------------------------------------------
// PASS 2: plasticity streaming. Per-element independent t-scan, recomputed
// with bit-identical FMA sequences from out_r (rdan) + g_rkcT (rkc).
// grid (5, 48): blockIdx.x = m-group of 4 rows, blockIdx.y = batch.
// thread q<200 owns k-chunk float4 (k = 4q) for 4 m rows.
// ---------------------------------------------------------------------------
__global__ __launch_bounds__(256) void plast_kernel(
    const float* __restrict__ time_arr,
    const float* __restrict__ W_kc0,
    const float* __restrict__ wt0,
    float* __restrict__ out)
{
    const int q  = threadIdx.x;
    if (q >= 200) return;
    const int mg = blockIdx.x;           // 0..4
    const int b  = blockIdx.y;           // 0..47
    const int m0 = mg * 4;

    const float* out_r  = out;
    float* out_W  = out + (long)TT * BB * NREC;
    float* out_wt = out_W + (long)TT * BB * NMBON * NKC;

    const float dt  = time_arr[1] - time_arr[0];
    const float a_w = dt * 0.2f;

    const float* rkc_g = g_rkcT + (long)b * TT * NKC;

    float4 W[4], wt[4];
    float  rb[4];
    {
        const long ib  = ((long)b * NMBON + m0) * NKC + q * 4;
        const long ob0 = ((long)b) * (NMBON * NKC) + (long)m0 * NKC + q * 4;
#pragma unroll
        for (int mm = 0; mm < 4; ++mm) {
            W[mm]  = *(const float4*)(W_kc0 + ib + (long)mm * NKC);
            wt[mm] = *(const float4*)(wt0   + ib + (long)mm * NKC);
            *(float4*)(out_W  + ob0 + (long)mm * NKC) = W[mm];
            *(float4*)(out_wt + ob0 + (long)mm * NKC) = wt[mm];
            rb[mm] = 0.1f;
        }
    }
    float4 bk = *(const float4*)(rkc_g + q * 4);   // rb_kc before step 0 = rkc(0)

    // prefetch t = 0 inputs
    float4 kc = bk;
    float  rdn[4];
#pragma unroll
    for (int mm = 0; mm < 4; ++mm)
        rdn[mm] = out_r[((long)1 * BB + b) * NREC + 80 + m0 + mm];

    for (int t = 0; t < NSTEP; ++t) {
        // prefetch next step's inputs (independent of this step's compute)
        float4 kc_n = kc;
        float  rdn_n[4];
        if (t + 1 < NSTEP) {
            kc_n = *(const float4*)(rkc_g + (long)(t + 1) * NKC + q * 4);
#pragma unroll
            for (int mm = 0; mm < 4; ++mm)
                rdn_n[mm] = out_r[((long)(t + 2) * BB + b) * NREC + 80 + m0 + mm];
        }

        // rb_kc(t) update (same order as pass 1 staging)
        bk.x = fmaf(a_w, kc.x - bk.x, bk.x);
        bk.y = fmaf(a_w, kc.y - bk.y, bk.y);
        bk.z = fmaf(a_w, kc.z - bk.z, bk.z);
        bk.w = fmaf(a_w, kc.w - bk.w, bk.w);

        const long ob = ((long)(t + 1) * BB + b) * (NMBON * NKC) + (long)m0 * NKC + q * 4;
#pragma unroll
        for (int mm = 0; mm < 4; ++mm) {
            const float rd = rdn[mm];
            rb[mm] = fmaf(a_w, rd - rb[mm], rb[mm]);   // rb_dan_new (same as pass 1)
            const float rbd = rb[mm];
            float4 w = W[mm], wv = wt[mm];
            float dw;
            dw = fmaf(rbd, kc.x, -(rd * bk.x)); wv.x = fmaf(dw, dt, wv.x);
            dw = fmaf(rbd, kc.y, -(rd * bk.y)); wv.y = fmaf(dw, dt, wv.y);
            dw = fmaf(rbd, kc.z, -(rd * bk.z)); wv.z = fmaf(dw, dt, wv.z);
            dw = fmaf(rbd, kc.w, -(rd * bk.w)); wv.w = fmaf(dw, dt, wv.w);
            w.x = fminf(fmaxf(fmaf(a_w, wv.x - w.x, w.x), 0.f), W_MAXC);
            w.y = fminf(fmaxf(fmaf(a_w, wv.y - w.y, w.y), 0.f), W_MAXC);
            w.z = fminf(fmaxf(fmaf(a_w, wv.z - w.z, w.z), 0.f), W_MAXC);
            w.w = fminf(fmaxf(fmaf(a_w, wv.w - w.w, w.w), 0.f), W_MAXC);
            W[mm] = w; wt[mm] = wv;
            *(float4*)(out_W  + ob + (long)mm * NKC) = w;
            *(float4*)(out_wt + ob + (long)mm * NKC) = wv;
        }

        kc = kc_n;
#pragma unroll
        for (int mm = 0; mm < 4; ++mm) rdn[mm] = rdn_n[mm];
    }
}

// ---------------------------------------------------------------------------
extern "C" void kernel_launch(void* const* d_in, const int* in_sizes, int n_in,
                              void* d_out, int out_size) {
    const float* r_kc      = (const float*)d_in[0];
    const float* r_ext     = (const float*)d_in[1];
    const float* time_arr  = (const float*)d_in[2];
    const float* W_kc0     = (const float*)d_in[3];
    const float* wt0       = (const float*)d_in[4];
    const float* W_recur   = (const float*)d_in[5];
    const float* W_readout = (const float*)d_in[6];
    const float* bias      = (const float*)d_in[7];
    const float* W_ext     = (const float*)d_in[8];
    float* out = (float*)d_out;

    cudaFuncSetAttribute(rnn_kernel, cudaFuncAttributeMaxDynamicSharedMemorySize,
                         SM_FLOATS * (int)sizeof(float));

    transpose_kernel<<<dim3(4, 25, BB), dim3(32, 32)>>>(r_kc);
    rnn_kernel<<<NCTA, NTHREADS, SM_FLOATS * (int)sizeof(float)>>>(
        r_ext, time_arr, W_kc0, wt0, W_recur, W_readout, bias, W_ext, out);
    plast_kernel<<<dim3(5, BB), 256>>>(time_arr, W_kc0, wt0, out);
}